// round 10
// baseline (speedup 1.0000x reference)
#include <cuda_runtime.h>

constexpr int Wd = 1024, Hd = 1024;
constexpr long HW = (long)Wd * Hd;
constexpr int CIN = 18;
constexpr float L2E = 1.4426950408889634f;

// Tile: 8 ch x 10 rows x 72 cols = 23,040 B (block covers 64px x 4 rows)
constexpr int TPX  = 72;
constexpr int TROW = 10;
constexpr int TCH  = TROW * TPX;           // 720

using u64 = unsigned long long;

__device__ __forceinline__ u64 pack2(float lo, float hi) {
    u64 r; asm("mov.b64 %0,{%1,%2};" : "=l"(r) : "f"(lo), "f"(hi)); return r;
}
__device__ __forceinline__ void unpack2(u64 v, float& lo, float& hi) {
    asm("mov.b64 {%0,%1},%2;" : "=f"(lo), "=f"(hi) : "l"(v));
}
__device__ __forceinline__ u64 fma2(u64 a, u64 b, u64 c) {
    u64 d; asm("fma.rn.f32x2 %0,%1,%2,%3;" : "=l"(d) : "l"(a), "l"(b), "l"(c)); return d;
}
__device__ __forceinline__ u64 mul2(u64 a, u64 b) {
    u64 d; asm("mul.rn.f32x2 %0,%1,%2;" : "=l"(d) : "l"(a), "l"(b)); return d;
}
__device__ __forceinline__ u64 add2(u64 a, u64 b) {
    u64 d; asm("add.rn.f32x2 %0,%1,%2;" : "=l"(d) : "l"(a), "l"(b)); return d;
}
__device__ __forceinline__ float ex2(float x) {
    float r; asm("ex2.approx.f32 %0,%1;" : "=f"(r) : "f"(x)); return r;
}
__device__ __forceinline__ u64 bcast2(float x) {
    unsigned u = __float_as_uint(x); return ((u64)u << 32) | u;
}
// (hi of a, lo of b) — the misaligned sliding pair
__device__ __forceinline__ u64 crosspair(u64 a, u64 b) {
    float al, ah, bl, bh;
    unpack2(a, al, ah); unpack2(b, bl, bh);
    return pack2(ah, bl);
}

// ---------------------------------------------------------------------------
// Interior: 2 px/thread (one f32x2 lane). Block = 32 lanes x 4 rows = 64px x 4.
// Window floats come from smem as 5 aligned LDS.64 (e[0..4] = floats 2g..2g+9);
// odd-tap pairs are e[] directly, even-tap pairs via crosspair. Horner form.
// ---------------------------------------------------------------------------
__device__ __forceinline__ void interior_path(const float* __restrict__ in,
                                              float* __restrict__ out,
                                              float* __restrict__ tile,
                                              int bx, int byi, int bz)
{
    const int g   = threadIdx.x;                 // 0..31 lane (x-pair)
    const int ty  = threadIdx.y;                 // 0..3
    const int tid = ty * 32 + g;
    const int gp  = bx * 32 + g;                 // global x-pair 0..511
    const int x0  = 4 + gp * 2;
    const int y   = 3 + byi * 4 + ty;

    const float* base = in + (long)bz * CIN * HW;

    // ---- Stage tile: 8ch x 10 rows x 18 float4 = 1440 ----
    {
        const int tx0 = bx * 64;
        const int gy0 = byi * 4;
        for (int idx = tid; idx < 1440; idx += 128) {
            const int row = idx / 18;
            const int k   = idx - row * 18;
            const int c   = row / TROW;
            const int r   = row - c * TROW;
            int gx = tx0 + k * 4; if (gx > 1020) gx = 1020;   // clamped: unused
            int gy = gy0 + r;     if (gy > 1023) gy = 1023;   // clamped: unused
            float4 v = *(const float4*)(base + c * HW + (long)gy * Wd + gx);
            *(float4*)(tile + c * TCH + r * TPX + k * 4) = v;
        }
    }
    __syncthreads();
    if (gp > 507 || y > 1020) return;

    const long ctr = (long)y * Wd + x0;

    // ---- Per-pixel params (f32x2 lanes) ----
    u64 rp2[8], mf2[8], K2 = 0, sxl2, syl2;
    {
        const u64 nL2E = bcast2(-L2E);
        const u64 m2   = bcast2(-2.f);
        #pragma unroll
        for (int c = 0; c < 8; ++c) {
            // center pair from tile (offset 2g+4, even -> aligned LDS.64)
            u64 f2 = *(const u64*)(tile + c * TCH + (ty + 3) * TPX + 2 * g + 4);
            u64 p2 = *(const u64*)(base + (8 + c) * HW + ctr);
            u64 r2 = mul2(mul2(p2, p2), nL2E);           // -(p^2)*log2(e)
            rp2[c] = r2;
            u64 rf = mul2(r2, f2);
            mf2[c] = mul2(rf, m2);                       // -2*rp*f
            K2     = fma2(rf, f2, K2);                   // += rp*f^2
        }
        u64 sv = *(const u64*)(base + 16 * HW + ctr);
        u64 tv = *(const u64*)(base + 17 * HW + ctr);
        sxl2 = mul2(mul2(sv, sv), nL2E);
        syl2 = mul2(mul2(tv, tv), nL2E);
    }

    u64 acc2[3] = {}, ws2 = 0;
    u64 kp[3][5];                     // e-form windows of output ch 0..2
    const int eoff0 = ty * TPX + 2 * g;

    #pragma unroll 1       // keep body inside I$ L1.5
    for (int i = 0; i < 7; ++i) {
        const int eo = eoff0 + i * TPX;
        const u64 dyb = bcast2((float)((i - 3) * (i - 3)));
        const u64 kd  = fma2(syl2, dyb, K2);

        u64 s2[7];

        // channel order: 3,4,5,6,7,0,1,2 (output channels last; ch2 e's stay hot)
        #pragma unroll
        for (int cc = 0; cc < 8; ++cc) {
            const int c = (cc < 5) ? cc + 3 : cc - 5;
            const float* rp = tile + c * TCH + eo;
            u64 e0 = *(const u64*)(rp);
            u64 e1 = *(const u64*)(rp + 2);
            u64 e2 = *(const u64*)(rp + 4);
            u64 e3 = *(const u64*)(rp + 6);
            u64 e4 = *(const u64*)(rp + 8);
            if (cc >= 5) {
                kp[cc - 5][0] = e0; kp[cc - 5][1] = e1; kp[cc - 5][2] = e2;
                kp[cc - 5][3] = e3; kp[cc - 5][4] = e4;
            }
            u64 pr[7];
            pr[0] = crosspair(e0, e1);
            pr[1] = e1;
            pr[2] = crosspair(e1, e2);
            pr[3] = e2;
            pr[4] = crosspair(e2, e3);
            pr[5] = e3;
            pr[6] = crosspair(e3, e4);
            const u64 rpc = rp2[c], mfc = mf2[c];
            if (cc == 0) {
                #pragma unroll
                for (int j = 0; j < 7; ++j)
                    s2[j] = fma2(pr[j], fma2(rpc, pr[j], mfc), kd);
            } else {
                #pragma unroll
                for (int j = 0; j < 7; ++j)
                    s2[j] = fma2(pr[j], fma2(rpc, pr[j], mfc), s2[j]);
            }
        }

        // Weights + fused accumulation
        #pragma unroll
        for (int j = 0; j < 7; ++j) {
            const u64 dxb = bcast2((float)((j - 3) * (j - 3)));
            u64 lw = fma2(sxl2, dxb, s2[j]);
            float a, b; unpack2(lw, a, b);
            u64 w2 = pack2(ex2(a), ex2(b));
            ws2 = add2(ws2, w2);
            #pragma unroll
            for (int ch = 0; ch < 3; ++ch) {
                u64 pairj = (j & 1) ? kp[ch][(j + 1) >> 1]
                                    : crosspair(kp[ch][j >> 1], kp[ch][(j >> 1) + 1]);
                acc2[ch] = fma2(w2, pairj, acc2[ch]);
            }
        }
    }

    float w0, w1; unpack2(ws2, w0, w1);
    const float i0 = 1.f / w0, i1 = 1.f / w1;

    float* ob = out + (long)bz * 3 * HW + ctr;
    #pragma unroll
    for (int c = 0; c < 3; ++c) {
        float a0, a1; unpack2(acc2[c], a0, a1);
        float2 o; o.x = a0 * i0; o.y = a1 * i1;
        *(float2*)(ob + c * HW) = o;
    }
}

// ---------------------------------------------------------------------------
// Border ring: 14288 px/batch, bounds-checked; blocks scheduled first.
// ---------------------------------------------------------------------------
__device__ __forceinline__ void border_path(const float* __restrict__ in,
                                            float* __restrict__ out,
                                            int bid, int bz)
{
    const int tid = threadIdx.y * 32 + threadIdx.x;
    int r = bid * 128 + tid;
    if (r >= 14288) return;
    int x, y;
    if (r < 3072)        { y = r >> 10;                x = r & 1023; }
    else if (r < 6144)   { r -= 3072;  y = 1021 + (r >> 10); x = r & 1023; }
    else if (r < 10216)  { r -= 6144;  y = 3 + (r >> 2);     x = r & 3; }
    else                 { r -= 10216; y = 3 + (r >> 2);     x = 1020 + (r & 3); }

    const float* base = in + (long)bz * CIN * HW;
    const long ctr = (long)y * Wd + x;

    float f[8], rp[8];
    #pragma unroll
    for (int c = 0; c < 8; ++c) {
        f[c] = base[c * HW + ctr];
        float pv = base[(8 + c) * HW + ctr];
        rp[c] = -(pv * pv);
    }
    float sv = base[16 * HW + ctr];
    float tv = base[17 * HW + ctr];
    const float sxl = -(sv * sv), syl = -(tv * tv);

    float a0 = 0.f, a1 = 0.f, a2 = 0.f, ws = 0.f;
    for (int i = 0; i < 7; ++i) {
        const int gy = y + i - 3;
        if (gy < 0 || gy >= Hd) continue;
        const float dy2 = (float)((i - 3) * (i - 3));
        for (int j = 0; j < 7; ++j) {
            const int gx = x + j - 3;
            if (gx < 0 || gx >= Wd) continue;
            const float dx2 = (float)((j - 3) * (j - 3));
            const float* q = base + (long)gy * Wd + gx;
            float fn[8];
            float lw = fmaf(sxl, dx2, syl * dy2);
            #pragma unroll
            for (int c = 0; c < 8; ++c) {
                fn[c] = q[c * HW];
                float d = fn[c] - f[c];
                lw = fmaf(rp[c], d * d, lw);
            }
            float w = __expf(lw);
            ws += w;
            a0 = fmaf(w, fn[0], a0);
            a1 = fmaf(w, fn[1], a1);
            a2 = fmaf(w, fn[2], a2);
        }
    }
    float* ob = out + (long)bz * 3 * HW + ctr;
    const float inv = 1.f / ws;
    ob[0]      = a0 * inv;
    ob[HW]     = a1 * inv;
    ob[2 * HW] = a2 * inv;
}

__global__ __launch_bounds__(128, 4)
void bilat_fused(const float* __restrict__ in, float* __restrict__ out)
{
    __shared__ __align__(16) float tile[8 * TCH];    // 23,040 B

    if (blockIdx.y < 7) {
        border_path(in, out, blockIdx.y * 16 + blockIdx.x, blockIdx.z);
    } else {
        interior_path(in, out, tile, blockIdx.x, blockIdx.y - 7, blockIdx.z);
    }
}

extern "C" void kernel_launch(void* const* d_in, const int* in_sizes, int n_in,
                              void* d_out, int out_size)
{
    const float* in = (const float*)d_in[0];
    float* out = (float*)d_out;

    dim3 blk(32, 4, 1);
    // x: 16 blocks (512 x-pairs, 508 used). y: 7 border rows (112 blocks) + 255 interior.
    dim3 grd(16, 7 + 255, 2);
    bilat_fused<<<grd, blk>>>(in, out);
}